// round 1
// baseline (speedup 1.0000x reference)
#include <cuda_runtime.h>
#include <math.h>

// Problem constants
#define B_    512
#define NS    128
#define IN_   2048
#define MEM_  64
#define OUT_  2048
#define RCOLS 65          // MEM_+1 columns of W_r
#define KO    2176        // IN_ + 2*MEM_ (W_o rows)

// ------------------------------------------------------------------
// Scratch (device globals; harness forbids allocation)
// ------------------------------------------------------------------
__device__ float g_q  [B_ * MEM_];    // x @ W_ar + b_ar
__device__ float g_xf [B_];           // x @ W_f[:IN] + b_f
__device__ float g_xr [B_ * RCOLS];   // x @ W_r[:IN] + b_r
__device__ float g_act[B_ * MEM_];    // active recall
__device__ float g_pas[B_ * MEM_];    // passive recall

// ==================================================================
// Kernel A: fused projections of x.
// grid = 128 (4 batch rows per block), 256 threads.
// Thread t < 130 owns one output column across GROUP rows:
//   t in [0,64)   -> q column t      (W_ar, stride 64)
//   t == 64       -> xf              (W_f,  stride 1)
//   t in [65,130) -> xr column t-65  (W_r,  stride 65)
// ==================================================================
#define GROUP 4
__global__ __launch_bounds__(256) void proj_kernel(
    const float* __restrict__ x,
    const float* __restrict__ W_ar, const float* __restrict__ b_ar,
    const float* __restrict__ W_f,  const float* __restrict__ b_f,
    const float* __restrict__ W_r,  const float* __restrict__ b_r)
{
    __shared__ float xs[GROUP][IN_];
    const int b0 = blockIdx.x * GROUP;

    // load GROUP x rows into smem (float4, coalesced)
    for (int i = threadIdx.x; i < GROUP * (IN_ / 4); i += blockDim.x) {
        int g = i / (IN_ / 4);
        int k4 = i % (IN_ / 4);
        ((float4*)xs[g])[k4] = ((const float4*)(x + (size_t)(b0 + g) * IN_))[k4];
    }
    __syncthreads();

    const int t = threadIdx.x;
    if (t < 130) {
        float acc[GROUP];
        #pragma unroll
        for (int g = 0; g < GROUP; g++) acc[g] = 0.f;

        const float* wcol;
        int stride;
        if (t < 64)      { wcol = W_ar + t;        stride = 64;    }
        else if (t == 64){ wcol = W_f;             stride = 1;     }
        else             { wcol = W_r + (t - 65);  stride = RCOLS; }

        #pragma unroll 8
        for (int k = 0; k < IN_; k++) {
            float w = __ldg(wcol + (size_t)k * stride);
            #pragma unroll
            for (int g = 0; g < GROUP; g++)
                acc[g] = fmaf(xs[g][k], w, acc[g]);
        }

        if (t < 64) {
            float bb = b_ar[t];
            #pragma unroll
            for (int g = 0; g < GROUP; g++)
                g_q[(size_t)(b0 + g) * MEM_ + t] = acc[g] + bb;
        } else if (t == 64) {
            float bb = b_f[0];
            #pragma unroll
            for (int g = 0; g < GROUP; g++)
                g_xf[b0 + g] = acc[g] + bb;
        } else {
            float bb = b_r[t - 65];
            #pragma unroll
            for (int g = 0; g < GROUP; g++)
                g_xr[(size_t)(b0 + g) * RCOLS + (t - 65)] = acc[g] + bb;
        }
    }
}

// ==================================================================
// Kernel B: everything that touches `memory`, fused.
// grid = 512 (one block per batch row), 256 threads, dyn smem ~86KB.
//   Phase 1: active/passive recall (scores, softmax, weighted sums)
//   Phase 2: rem = xr + mem @ Wr2 ; forget = 1.1*sigmoid(xf + mem@Wf2)
//   Phase 3: new_memory = mem*forget + rem[64]*rem[:64]
// memory tile kept in smem with pitch 65 (odd -> conflict-free col reads)
// ==================================================================
__device__ __forceinline__ float blockReduce256(float v, float* red8, int isSum)
{
    #pragma unroll
    for (int o = 16; o; o >>= 1) {
        float u = __shfl_xor_sync(0xffffffffu, v, o);
        v = isSum ? (v + u) : fmaxf(v, u);
    }
    if ((threadIdx.x & 31) == 0) red8[threadIdx.x >> 5] = v;
    __syncthreads();
    float r = red8[0];
    #pragma unroll
    for (int i = 1; i < 8; i++) r = isSum ? (r + red8[i]) : fmaxf(r, red8[i]);
    __syncthreads();
    return r;
}

__global__ __launch_bounds__(256) void mem_kernel(
    const float* __restrict__ memory,
    const float* __restrict__ W_pr, const float* __restrict__ b_pr,
    const float* __restrict__ W_f,
    const float* __restrict__ W_r,
    float* __restrict__ new_memory)
{
    extern __shared__ float sm[];
    float* ms   = sm;               // 128*65 = 8320
    float* ws   = ms  + 8320;       // 64*66  = 4224  (Wr2 | Wf2 fused, pitch 66)
    float* rem  = ws  + 4224;       // 128*66 = 8448  (cols 0..64 rem, col 65 forget)
    float* qs   = rem + 8448;       // 64
    float* wpr  = qs  + 64;         // 64
    float* xrs  = wpr + 64;         // 66
    float* s1   = xrs + 66;         // 128
    float* s2   = s1  + 128;        // 128
    float* red8 = s2  + 128;        // 8

    const int b = blockIdx.x;
    const int t = threadIdx.x;
    const float* memb = memory + (size_t)b * NS * MEM_;

    // ---- loads ----
    for (int i = t; i < NS * MEM_; i += 256) {
        int n = i >> 6, m = i & 63;
        ms[n * 65 + m] = memb[i];
    }
    for (int i = t; i < 64 * 66; i += 256) {
        int k = i / 66, j = i - k * 66;
        ws[i] = (j < 65) ? W_r[(size_t)(IN_ + k) * RCOLS + j] : W_f[IN_ + k];
    }
    if (t < 64)  { qs[t] = g_q[(size_t)b * MEM_ + t]; wpr[t] = W_pr[t]; }
    if (t < 65)  { xrs[t] = g_xr[(size_t)b * RCOLS + t]; }
    __syncthreads();

    // ---- Phase 1: scores ----
    float s1v = -1e30f, s2v = -1e30f;
    if (t < NS) {
        float a = 0.f, p = 0.f;
        #pragma unroll 8
        for (int k = 0; k < MEM_; k++) {
            float mv = ms[t * 65 + k];
            a = fmaf(mv, qs[k], a);
            p = fmaf(mv, wpr[k], p);
        }
        s1v = a;
        s2v = p + b_pr[0];
    }
    float max1 = blockReduce256(s1v, red8, 0);
    float max2 = blockReduce256(s2v, red8, 0);
    float e1 = (t < NS) ? expf(s1v - max1) : 0.f;
    float e2 = (t < NS) ? expf(s2v - max2) : 0.f;
    float sum1 = blockReduce256(e1, red8, 1);
    float sum2 = blockReduce256(e2, red8, 1);
    if (t < NS) { s1[t] = e1 / sum1; s2[t] = e2 / sum2; }
    __syncthreads();

    if (t < MEM_) {
        float act = 0.f, pas = 0.f;
        #pragma unroll 4
        for (int n = 0; n < NS; n++) {
            float mv = ms[n * 65 + t];
            act = fmaf(s1[n], mv, act);
            pas = fmaf(s2[n], mv, pas);
        }
        g_act[(size_t)b * MEM_ + t] = act;
        g_pas[(size_t)b * MEM_ + t] = pas;
    }

    // ---- Phase 2: rem + forget (thread owns one of 66 columns, 2 n-groups) ----
    if (t < 132) {
        const int j   = t % 66;
        const int nlo = (t / 66) * 64;
        float w[64];
        #pragma unroll
        for (int k = 0; k < 64; k++) w[k] = ws[k * 66 + j];
        const float base = (j < 65) ? xrs[j] : g_xf[b];
        #pragma unroll 2
        for (int n = nlo; n < nlo + 64; n++) {
            float acc = base;
            #pragma unroll
            for (int k = 0; k < 64; k++)
                acc = fmaf(ms[n * 65 + k], w[k], acc);
            if (j < 65) rem[n * 66 + j] = acc;
            else        rem[n * 66 + 65] = 1.1f / (1.f + expf(-acc));   // forget
        }
    }
    __syncthreads();

    // ---- Phase 3: gated update ----
    float* nm = new_memory + (size_t)b * NS * MEM_;
    for (int i = t; i < NS * MEM_; i += 256) {
        int n = i >> 6, m = i & 63;
        float f    = rem[n * 66 + 65];
        float gate = rem[n * 66 + 64];
        nm[i] = fmaf(ms[n * 65 + m], f, gate * rem[n * 66 + m]);
    }
}

// ==================================================================
// Kernel C: output = [x | active | passive] @ W_o + b_o
// [512,2176] x [2176,2048]. Tiled fp32 GEMM: 64x64x16, 4x4 microtile.
// ==================================================================
__global__ __launch_bounds__(256) void out_gemm(
    const float* __restrict__ x,
    const float* __restrict__ W_o, const float* __restrict__ b_o,
    float* __restrict__ out)
{
    __shared__ float As[16 * 65];   // As[kk*65 + row], pitch 65 kills store conflicts
    __shared__ float Bs[16 * 64];   // Bs[kk*64 + col]

    const int br = blockIdx.y * 64;
    const int bc = blockIdx.x * 64;
    const int tx = threadIdx.x & 15;       // 16 col-groups
    const int ty = threadIdx.x >> 4;       // 16 row-groups

    float acc[4][4];
    #pragma unroll
    for (int i = 0; i < 4; i++)
        #pragma unroll
        for (int j = 0; j < 4; j++) acc[i][j] = 0.f;

    for (int k0 = 0; k0 < KO; k0 += 16) {
        // A tile: 64 rows x 16 k
        {
            int kk = threadIdx.x & 15;
            int r0 = threadIdx.x >> 4;
            int gk = k0 + kk;
            #pragma unroll
            for (int p = 0; p < 4; p++) {
                int row = r0 + p * 16;
                int gb  = br + row;
                float v;
                if (gk < IN_)            v = x[(size_t)gb * IN_ + gk];
                else if (gk < IN_ + 64)  v = g_act[(size_t)gb * MEM_ + (gk - IN_)];
                else                     v = g_pas[(size_t)gb * MEM_ + (gk - IN_ - 64)];
                As[kk * 65 + row] = v;
            }
        }
        // B tile: 16 k x 64 cols (coalesced)
        {
            int nn = threadIdx.x & 63;
            int kk0 = threadIdx.x >> 6;
            #pragma unroll
            for (int p = 0; p < 4; p++) {
                int kk = kk0 + p * 4;
                Bs[kk * 64 + nn] = W_o[(size_t)(k0 + kk) * OUT_ + bc + nn];
            }
        }
        __syncthreads();

        #pragma unroll
        for (int kk = 0; kk < 16; kk++) {
            float a0 = As[kk * 65 + ty * 4 + 0];
            float a1 = As[kk * 65 + ty * 4 + 1];
            float a2 = As[kk * 65 + ty * 4 + 2];
            float a3 = As[kk * 65 + ty * 4 + 3];
            float4 bv = *(const float4*)&Bs[kk * 64 + tx * 4];
            acc[0][0] = fmaf(a0, bv.x, acc[0][0]); acc[0][1] = fmaf(a0, bv.y, acc[0][1]);
            acc[0][2] = fmaf(a0, bv.z, acc[0][2]); acc[0][3] = fmaf(a0, bv.w, acc[0][3]);
            acc[1][0] = fmaf(a1, bv.x, acc[1][0]); acc[1][1] = fmaf(a1, bv.y, acc[1][1]);
            acc[1][2] = fmaf(a1, bv.z, acc[1][2]); acc[1][3] = fmaf(a1, bv.w, acc[1][3]);
            acc[2][0] = fmaf(a2, bv.x, acc[2][0]); acc[2][1] = fmaf(a2, bv.y, acc[2][1]);
            acc[2][2] = fmaf(a2, bv.z, acc[2][2]); acc[2][3] = fmaf(a2, bv.w, acc[2][3]);
            acc[3][0] = fmaf(a3, bv.x, acc[3][0]); acc[3][1] = fmaf(a3, bv.y, acc[3][1]);
            acc[3][2] = fmaf(a3, bv.z, acc[3][2]); acc[3][3] = fmaf(a3, bv.w, acc[3][3]);
        }
        __syncthreads();
    }

    #pragma unroll
    for (int i = 0; i < 4; i++) {
        int row = br + ty * 4 + i;
        #pragma unroll
        for (int j = 0; j < 4; j++) {
            int col = bc + tx * 4 + j;
            out[(size_t)row * OUT_ + col] = acc[i][j] + b_o[col];
        }
    }
}

// ==================================================================
// Launch
// ==================================================================
extern "C" void kernel_launch(void* const* d_in, const int* in_sizes, int n_in,
                              void* d_out, int out_size)
{
    const float* x    = (const float*)d_in[0];
    const float* mem  = (const float*)d_in[1];
    const float* W_ar = (const float*)d_in[2];
    const float* b_ar = (const float*)d_in[3];
    const float* W_pr = (const float*)d_in[4];
    const float* b_pr = (const float*)d_in[5];
    const float* W_f  = (const float*)d_in[6];
    const float* b_f  = (const float*)d_in[7];
    const float* W_r  = (const float*)d_in[8];
    const float* b_r  = (const float*)d_in[9];
    const float* W_o  = (const float*)d_in[10];
    const float* b_o  = (const float*)d_in[11];

    float* out     = (float*)d_out;                     // [512, 2048]
    float* new_mem = out + (size_t)B_ * OUT_;           // [512, 128, 64]

    // Kernel A: projections of x
    proj_kernel<<<B_ / GROUP, 256>>>(x, W_ar, b_ar, W_f, b_f, W_r, b_r);

    // Kernel B: memory-fused (recalls + gated update)
    static bool attr_done = false;
    const int smemB = (8320 + 4224 + 8448 + 64 + 64 + 66 + 128 + 128 + 8) * 4; // 85800 B
    if (!attr_done) {
        cudaFuncSetAttribute(mem_kernel,
                             cudaFuncAttributeMaxDynamicSharedMemorySize, smemB);
        attr_done = true;
    }
    mem_kernel<<<B_, 256, smemB>>>(mem, W_pr, b_pr, W_f, W_r, new_mem);

    // Kernel C: output GEMM
    dim3 gridC(OUT_ / 64, B_ / 64);
    out_gemm<<<gridC, 256>>>(x, W_o, b_o, out);
}